// round 13
// baseline (speedup 1.0000x reference)
#include <cuda_runtime.h>

// WarpImage R13: R9 (measured optimum: scalar 4-tap gather, 32x16 tiles,
// 512 thr, 32 regs, unroll 4) + cache-policy hints:
//  - gather taps use ld.global.nc.L1::evict_last (image-window lines are
//    reused ~30x across warps in a block; keep them sticky in L1 to cut
//    the ~20% of L1 wavefronts that are L2->L1 fills),
//  - output stores use __stcs (write-once stream, evict-first in L2).
// Design-space results from R2-R12 sweeps in previous comments; border
// semantics: independently clamped taps + weight zeroing (rel_err 4.5e-8).

#define CC 32
#define HH 1024
#define WW 2048
#define HWSZ (HH * WW)

__device__ __forceinline__ float ldg_el(const float* p)
{
    float v;
    asm("ld.global.nc.L1::evict_last.f32 %0, [%1];" : "=f"(v) : "l"(p));
    return v;
}

__global__ __launch_bounds__(512, 4) void warp_image_kernel(
    const float* __restrict__ image,
    const float* __restrict__ flow,
    float* __restrict__ out)
{
    const int w = blockIdx.x * 32 + threadIdx.x;
    const int h = blockIdx.y * 16 + threadIdx.y;
    const int idx = h * WW + w;

    float u = (float)w + __ldg(flow + idx);
    float v = (float)h + __ldg(flow + HWSZ + idx);

    float u0f = floorf(u);
    float v0f = floorf(v);
    float wu = u - u0f;
    float wv = v - v0f;

    int u0 = (int)u0f;
    int v0 = (int)v0f;

    bool vu0 = (u0 >= 0) && (u0 <= WW - 1);
    bool vu1 = (u0 + 1 >= 0) && (u0 + 1 <= WW - 1);
    bool vv0 = (v0 >= 0) && (v0 <= HH - 1);
    bool vv1 = (v0 + 1 >= 0) && (v0 + 1 <= HH - 1);

    float w00 = (1.0f - wu) * (1.0f - wv); if (!(vu0 && vv0)) w00 = 0.0f;
    float w10 = wu * (1.0f - wv);          if (!(vu1 && vv0)) w10 = 0.0f;
    float w01 = (1.0f - wu) * wv;          if (!(vu0 && vv1)) w01 = 0.0f;
    float w11 = wu * wv;                   if (!(vu1 && vv1)) w11 = 0.0f;

    int u0c = min(max(u0, 0), WW - 1);
    int v0c = min(max(v0, 0), HH - 1);

    // compact tap addressing: clamp(x+1) = clamp(x) + d
    const int du  = ((u0 >= 0) && (u0 <= WW - 2)) ? 1 : 0;
    const int dvW = ((v0 >= 0) && (v0 <= HH - 2)) ? WW : 0;

    const float* g = image + (v0c * WW + u0c);   // tap (v0,u0), channel 0
    float* o = out + idx;

    #pragma unroll 4
    for (int c = 0; c < CC; c++) {
        float t00 = ldg_el(g);
        float t10 = ldg_el(g + du);
        float t01 = ldg_el(g + dvW);
        float t11 = ldg_el(g + dvW + du);
        __stcs(o, w00 * t00 + w10 * t10 + w01 * t01 + w11 * t11);
        g += HWSZ;
        o += HWSZ;
    }
}

extern "C" void kernel_launch(void* const* d_in, const int* in_sizes, int n_in,
                              void* d_out, int out_size)
{
    const float* image = (const float*)d_in[0];
    const float* flow  = (const float*)d_in[1];
    float* out = (float*)d_out;

    cudaFuncSetAttribute(warp_image_kernel,
                         cudaFuncAttributePreferredSharedMemoryCarveout, 0);

    dim3 block(32, 16);
    dim3 grid(WW / 32, HH / 16);   // (64, 64)
    warp_image_kernel<<<grid, block>>>(image, flow, out);
}

// round 14
// speedup vs baseline: 1.0032x; 1.0032x over previous
#include <cuda_runtime.h>

// WarpImage FINAL (R9 configuration — measured optimum over 13 rounds).
// Bilinear warp: image [32,1024,2048] f32 + flow [2,1024,2048] f32
//   -> out [32,1024,2048] f32, border value 0.
//
// Structure: one thread per pixel, scalar 4-tap direct gather, loop over 32
// channels (weights/addresses computed once, reused 32x). 32x16 pixel tiles
// (512-thread blocks), 32 regs, 4 CTAs/SM, channel unroll 4 (16 loads in
// flight = exact fit of the register budget).
//
// Measured design space (bench us):
//   this=130.0 | 8-row tile=132 | 32-row tile=133.9 | unroll8=193 |
//   f32x2 tap merge=159 | f32x4 tap merge=244 | smem staging=260 |
//   4px/thread=150 | evict_last/stcs hints=neutral.
// Hardware invariants derived: divergent-gather L1 cost ~ bytes/lane
// (scalar LDG.32 optimal); l1tex util ceiling ~84%; resulting floor ~128us
// (ncu), which this kernel achieves. DRAM traffic is at the compulsory
// level (~530MB, 50% of peak BW) — no redundant traffic remains.
//
// Border semantics (exact reference match, rel_err 4.5e-8): each tap
// independently clamped via clamp(x+1) = clamp(x) + d, out-of-image taps
// zeroed through their weights.

#define CC 32
#define HH 1024
#define WW 2048
#define HWSZ (HH * WW)

__global__ __launch_bounds__(512, 4) void warp_image_kernel(
    const float* __restrict__ image,
    const float* __restrict__ flow,
    float* __restrict__ out)
{
    const int w = blockIdx.x * 32 + threadIdx.x;
    const int h = blockIdx.y * 16 + threadIdx.y;
    const int idx = h * WW + w;

    float u = (float)w + __ldg(flow + idx);
    float v = (float)h + __ldg(flow + HWSZ + idx);

    float u0f = floorf(u);
    float v0f = floorf(v);
    float wu = u - u0f;
    float wv = v - v0f;

    int u0 = (int)u0f;
    int v0 = (int)v0f;

    bool vu0 = (u0 >= 0) && (u0 <= WW - 1);
    bool vu1 = (u0 + 1 >= 0) && (u0 + 1 <= WW - 1);
    bool vv0 = (v0 >= 0) && (v0 <= HH - 1);
    bool vv1 = (v0 + 1 >= 0) && (v0 + 1 <= HH - 1);

    float w00 = (1.0f - wu) * (1.0f - wv); if (!(vu0 && vv0)) w00 = 0.0f;
    float w10 = wu * (1.0f - wv);          if (!(vu1 && vv0)) w10 = 0.0f;
    float w01 = (1.0f - wu) * wv;          if (!(vu0 && vv1)) w01 = 0.0f;
    float w11 = wu * wv;                   if (!(vu1 && vv1)) w11 = 0.0f;

    int u0c = min(max(u0, 0), WW - 1);
    int v0c = min(max(v0, 0), HH - 1);

    // compact tap addressing: clamp(x+1) = clamp(x) + d
    const int du  = ((u0 >= 0) && (u0 <= WW - 2)) ? 1 : 0;
    const int dvW = ((v0 >= 0) && (v0 <= HH - 2)) ? WW : 0;

    const float* g = image + (v0c * WW + u0c);   // tap (v0,u0), channel 0
    float* o = out + idx;

    #pragma unroll 4
    for (int c = 0; c < CC; c++) {
        float t00 = __ldg(g);
        float t10 = __ldg(g + du);
        float t01 = __ldg(g + dvW);
        float t11 = __ldg(g + dvW + du);
        *o = w00 * t00 + w10 * t10 + w01 * t01 + w11 * t11;
        g += HWSZ;
        o += HWSZ;
    }
}

extern "C" void kernel_launch(void* const* d_in, const int* in_sizes, int n_in,
                              void* d_out, int out_size)
{
    const float* image = (const float*)d_in[0];
    const float* flow  = (const float*)d_in[1];
    float* out = (float*)d_out;

    cudaFuncSetAttribute(warp_image_kernel,
                         cudaFuncAttributePreferredSharedMemoryCarveout, 0);

    dim3 block(32, 16);
    dim3 grid(WW / 32, HH / 16);   // (64, 64)
    warp_image_kernel<<<grid, block>>>(image, flow, out);
}